// round 9
// baseline (speedup 1.0000x reference)
#include <cuda_runtime.h>
#include <float.h>
#include <math.h>

#define N_PROT 50000
#define N_SUB  2000
#define D      256     // D_PROT == D_SUB
#define DP     128     // D_PROJ
#define KERN   16
#define N_INT  64
#define NW     (N_PROT - KERN + 1)   // 49985

#define NBLK    592       // 4 * 148 SMs — all resident (launch_bounds(256,4))
#define PCHUNK  3125      // prot chunks of 16 rows
#define SCHUNK  125       // sub  chunks of 16 rows
#define TCHUNK  (PCHUNK + SCHUNK + 1)
#define NB_WIN  196       // 196*256 = 50176 >= NW
#define N_RPART 8

// -------- device scratch (no allocations allowed) --------
__device__ float d_g[N_PROT];
__device__ float d_s[N_PROT];
__device__ float d_v[D];          // Wp @ w1
__device__ float d_u[D];          // Wp @ ones
__device__ float d_react_part[N_RPART * DP];
__device__ float d_blkVal[NB_WIN];
__device__ int   d_blkIdx[NB_WIN];
__device__ int   d_count;         // finalize ticket; reset by finalize
__device__ int   d_vu_done;       // v/u flag; reset by finalize
__device__ int   d_bar;           // barrier;  reset by finalize

__device__ __forceinline__ float dot4(float4 a, float4 b) {
    return a.x*b.x + a.y*b.y + a.z*b.z + a.w*b.w;
}

__global__ void __launch_bounds__(256, 4)
mega(const float* __restrict__ prot,
     const float* __restrict__ subn,
     const int*   __restrict__ idx,
     const float* __restrict__ Wp,
     const float* __restrict__ bp,
     const float* __restrict__ Ws,
     const float* __restrict__ bs,
     const float* __restrict__ wa,
     const float* __restrict__ sub_out,
     const float* __restrict__ prot_out,
     float* __restrict__ out)
{
    __shared__ float sv[D];           // staged v
    __shared__ float su[D];           // staged u
    __shared__ float sacc[8][32];
    __shared__ float ssumL[32];
    __shared__ float sg[256 + KERN];
    __shared__ float ss[256 + KERN];
    __shared__ float bval[256];
    __shared__ int   bidx[256];
    __shared__ int   s_last, s_top;
    __shared__ float attn[KERN];
    __shared__ float wrow[D];
    __shared__ float ts[DP];
    __shared__ float tpart[DP];
    __shared__ float dprot[D];
    __shared__ float dsub[D];

    int b    = blockIdx.x;
    int t    = threadIdx.x;
    int warp = t >> 5;
    int lane = t & 31;

    // ---------------- producer prologue ----------------
    if (b < 32) {
        // v/u: one warp per Wp row, single coalesced float4 load
        int row = b * 8 + warp;
        float4 w = ((const float4*)(Wp + (size_t)row * DP))[lane];
        float4 a = ((const float4*)wa)[lane];
        float vv = dot4(w, a);
        float uu = w.x + w.y + w.z + w.w;
        #pragma unroll
        for (int o = 16; o > 0; o >>= 1) {
            vv += __shfl_xor_sync(0xffffffffu, vv, o);
            uu += __shfl_xor_sync(0xffffffffu, uu, o);
        }
        if (lane == 0) { d_v[row] = vv; d_u[row] = uu; }
        __syncthreads();
        if (t == 0) { __threadfence(); atomicAdd(&d_vu_done, 1); }
    } else if (b < 32 + N_RPART) {
        // reaction partial over j-slice [j0, j0+32)
        int r  = b - 32;
        int j0 = r * 32;
        int col  = t & 31;
        int row8 = t >> 5;
        float acc = 0.f;
        #pragma unroll
        for (int p = 0; p < 8; p++)
            acc += subn[(size_t)idx[p * 8 + row8] * D + j0 + col];
        sacc[row8][col] = acc;
        __syncthreads();
        if (t < 32) {
            float s = 0.f;
            #pragma unroll
            for (int r8 = 0; r8 < 8; r8++) s += sacc[r8][t];
            ssumL[t] = s;
        }
        __syncthreads();
        if (t < DP) {
            float p = 0.f;
            #pragma unroll
            for (int j = 0; j < 32; j++)
                p += ssumL[j] * Ws[(j0 + j) * DP + t];
            d_react_part[r * DP + t] = p;
        }
    }

    // ---------------- stage v/u to shared (all blocks) ----------------
    if (t == 0)
        while (((volatile int*)&d_vu_done)[0] < 32) __nanosleep(32);
    __syncthreads();
    sv[t] = d_v[t];
    su[t] = d_u[t];
    __syncthreads();

    // ---------------- phase A: prot copy + g/s matvec (pipelined) ----------------
    {
        int chunk = b;
        if (chunk < PCHUNK) {
            float4 va = ((const float4*)sv)[lane];
            float4 vc = ((const float4*)sv)[lane + 32];
            float4 ua = ((const float4*)su)[lane];
            float4 uc = ((const float4*)su)[lane + 32];

            const float4* src = (const float4*)(prot + (size_t)(chunk * 16 + warp * 2) * D);
            float4 a0 = src[lane];
            float4 c0 = src[lane + 32];
            float4 a1 = src[64 + lane];
            float4 c1 = src[64 + lane + 32];

            while (true) {
                int nxt = chunk + NBLK;
                bool hn = nxt < PCHUNK;
                float4 n0, n1, n2, n3;
                if (hn) {
                    const float4* nsrc = (const float4*)(prot + (size_t)(nxt * 16 + warp * 2) * D);
                    n0 = nsrc[lane];
                    n1 = nsrc[lane + 32];
                    n2 = nsrc[64 + lane];
                    n3 = nsrc[64 + lane + 32];
                }

                int row = chunk * 16 + warp * 2;
                float4* dst = (float4*)(out + (size_t)row * D);
                dst[lane]           = a0;
                dst[lane + 32]      = c0;
                dst[64 + lane]      = a1;
                dst[64 + lane + 32] = c1;

                float g0 = dot4(a0, va) + dot4(c0, vc);
                float s0 = dot4(a0, ua) + dot4(c0, uc);
                float g1 = dot4(a1, va) + dot4(c1, vc);
                float s1 = dot4(a1, ua) + dot4(c1, uc);
                #pragma unroll
                for (int o = 16; o > 0; o >>= 1) {
                    g0 += __shfl_down_sync(0xffffffffu, g0, o);
                    s0 += __shfl_down_sync(0xffffffffu, s0, o);
                    g1 += __shfl_down_sync(0xffffffffu, g1, o);
                    s1 += __shfl_down_sync(0xffffffffu, s1, o);
                }
                if (lane == 0) {
                    d_g[row]     = g0;  d_s[row]     = s0;
                    d_g[row + 1] = g1;  d_s[row + 1] = s1;
                }

                if (!hn) break;
                a0 = n0; c0 = n1; a1 = n2; c1 = n3;
                chunk = nxt;
            }
        }
    }

    // ---------------- phase A': sub copy + idx tail ----------------
    for (int chunk = b; chunk < TCHUNK; chunk += NBLK) {
        if (chunk >= PCHUNK && chunk < PCHUNK + SCHUNK) {
            int row = (chunk - PCHUNK) * 16 + warp * 2;
            const float4* src = (const float4*)(subn + (size_t)row * D);
            float4*       dst = (float4*)(out + (size_t)(N_PROT + row) * D);
            dst[lane]           = src[lane];
            dst[lane + 32]      = src[lane + 32];
            dst[64 + lane]      = src[64 + lane];
            dst[64 + lane + 32] = src[64 + lane + 32];
        } else if (chunk == PCHUNK + SCHUNK) {
            if (t < N_INT)
                out[(size_t)(N_PROT + N_SUB) * D + t] = (float)idx[t];
        }
    }

    // ---------------- grid barrier (arrive; non-phase-B exit) ----------------
    __syncthreads();
    if (t == 0) {
        __threadfence();
        atomicAdd(&d_bar, 1);
    }
    if (b >= NB_WIN) return;
    if (t == 0) {
        while (((volatile int*)&d_bar)[0] < NBLK) __nanosleep(64);
        __threadfence();
    }
    __syncthreads();

    // ---------------- phase B: windows + block argmax ----------------
    {
        int base = b * 256;
        for (int i = t; i < 256 + KERN - 1; i += 256) {
            int gi = base + i;
            sg[i] = (gi < N_PROT) ? d_g[gi] : -FLT_MAX;
            ss[i] = (gi < N_PROT) ? d_s[gi] : 0.f;
        }
        __syncthreads();

        int   w = base + t;
        float A = -FLT_MAX;
        if (w < NW) {
            float m = sg[t];
            #pragma unroll
            for (int k = 1; k < KERN; k++) m = fmaxf(m, sg[t + k]);
            float wsum = 0.f, asum = 0.f;
            #pragma unroll
            for (int k = 0; k < KERN; k++) {
                float e = expf(sg[t + k] - m);
                wsum += e;
                asum += e * ss[t + k];
            }
            A = asum / wsum;
        }
        bval[t] = A;
        bidx[t] = w;
        __syncthreads();

        for (int off = 128; off > 0; off >>= 1) {
            if (t < off) {
                float ov = bval[t + off];
                int   oi = bidx[t + off];
                if (ov > bval[t] || (ov == bval[t] && oi < bidx[t])) {
                    bval[t] = ov;
                    bidx[t] = oi;
                }
            }
            __syncthreads();
        }
        if (t == 0) {
            d_blkVal[b] = bval[0];
            d_blkIdx[b] = bidx[0];
        }
    }

    // ---------------- ticket among phase-B blocks: last finalizes ----------------
    __syncthreads();
    if (t == 0) {
        __threadfence();
        s_last = (atomicAdd(&d_count, 1) == NB_WIN - 1);
    }
    __syncthreads();
    if (!s_last) return;

    // reduce 196 candidates -> top
    if (t < NB_WIN) { bval[t] = d_blkVal[t]; bidx[t] = d_blkIdx[t]; }
    else            { bval[t] = -FLT_MAX;    bidx[t] = 0x7fffffff; }
    __syncthreads();
    for (int off = 128; off > 0; off >>= 1) {
        if (t < off) {
            float ov = bval[t + off];
            int   oi = bidx[t + off];
            if (ov > bval[t] || (ov == bval[t] && oi < bidx[t])) {
                bval[t] = ov;
                bidx[t] = oi;
            }
        }
        __syncthreads();
    }
    if (t == 0) {
        s_top = bidx[0];
        d_count = 0; d_vu_done = 0; d_bar = 0;   // reset for graph replay
    }
    __syncthreads();
    int top = s_top;

    // attn (one warp)
    if (t < 32) {
        float gk = (t < KERN) ? d_g[top + t] : -FLT_MAX;
        float m = gk;
        #pragma unroll
        for (int o = 16; o > 0; o >>= 1)
            m = fmaxf(m, __shfl_xor_sync(0xffffffffu, m, o));
        float e = (t < KERN) ? expf(gk - m) : 0.f;
        float sum = e;
        #pragma unroll
        for (int o = 16; o > 0; o >>= 1)
            sum += __shfl_xor_sync(0xffffffffu, sum, o);
        if (t < KERN) attn[t] = e / sum;
    }
    __syncthreads();

    // weighted prot row
    {
        float acc = 0.f;
        #pragma unroll
        for (int k = 0; k < KERN; k++)
            acc += attn[k] * prot[(size_t)(top + k) * D + t];
        wrow[t] = acc;
    }
    __syncthreads();

    // top_score[d] = sum_r react_part[r][d] + 64*bs[d] + bp[d] + wrow @ Wp[:,d]
    {
        int c    = t & (DP - 1);
        int half = t >> 7;
        int j0   = half * (D / 2);
        float acc = 0.f;
        #pragma unroll 32
        for (int j = 0; j < D / 2; j++)
            acc += wrow[j0 + j] * Wp[(j0 + j) * DP + c];
        if (half) tpart[c] = acc;
        __syncthreads();
        if (!half) {
            float rp = 0.f;
            #pragma unroll
            for (int r = 0; r < N_RPART; r++) rp += d_react_part[r * DP + c];
            ts[c] = acc + tpart[c] + rp + (float)N_INT * bs[c] + bp[c];
        }
    }
    __syncthreads();

    // deltas
    {
        float dp_ = 0.f, ds_ = 0.f;
        #pragma unroll 32
        for (int d = 0; d < DP; d++) {
            float s = ts[d];
            dp_ += s * prot_out[d * D + t];
            ds_ += s * sub_out[d * D + t];
        }
        dprot[t] = dp_;
        dsub[t]  = ds_;
    }
    __syncthreads();

    // patch 16 prot rows
    #pragma unroll
    for (int k = 0; k < KERN; k++)
        out[(size_t)(top + k) * D + t] += dprot[t];

    // patch 64 sub rows (set semantics; duplicates identical)
    #pragma unroll 4
    for (int m = 0; m < N_INT; m++) {
        int r = idx[m];
        out[(size_t)(N_PROT + r) * D + t] = subn[(size_t)r * D + t] + dsub[t];
    }
}

// ============================================================
extern "C" void kernel_launch(void* const* d_in, const int* in_sizes, int n_in,
                              void* d_out, int out_size)
{
    const float* prot_node = (const float*)d_in[0];
    const float* sub_node  = (const float*)d_in[1];
    const int*   int_index = (const int*)  d_in[2];
    const float* Wp        = (const float*)d_in[3];
    const float* bp        = (const float*)d_in[4];
    const float* Ws        = (const float*)d_in[5];
    const float* bs        = (const float*)d_in[6];
    const float* wa        = (const float*)d_in[7];
    const float* sub_out   = (const float*)d_in[9];
    const float* prot_out  = (const float*)d_in[10];
    float*       out       = (float*)d_out;

    mega<<<NBLK, 256>>>(prot_node, sub_node, int_index, Wp, bp, Ws, bs, wa,
                        sub_out, prot_out, out);
}

// round 11
// speedup vs baseline: 1.0679x; 1.0679x over previous
#include <cuda_runtime.h>
#include <float.h>
#include <math.h>

#define N_PROT 50000
#define N_SUB  2000
#define D      256     // D_PROT == D_SUB
#define DP     128     // D_PROJ
#define KERN   16
#define N_INT  64
#define NW     (N_PROT - KERN + 1)   // 49985

#define NBLK    444       // 3 * 148 SMs — all resident (launch_bounds(256,3))
#define NB_WIN  196       // 196*256 = 50176 >= NW
#define N_RPART 8

#define TK_PROT 3125      // 16 prot rows per ticket
#define TK_SUB  125       // 16 sub  rows per ticket
#define NTICK   (TK_PROT + TK_SUB)

// -------- device scratch (no allocations allowed) --------
__device__ float d_g[N_PROT];
__device__ float d_s[N_PROT];
__device__ float d_v[D];          // Wp @ w1
__device__ float d_u[D];          // Wp @ ones
__device__ float d_react_part[N_RPART * DP];
__device__ float d_blkVal[NB_WIN];
__device__ int   d_blkIdx[NB_WIN];
__device__ int   d_work;          // steal ticket;    reset by finalize
__device__ int   d_count;         // finalize ticket; reset by finalize
__device__ int   d_vu_done;       // v/u flag;        reset by finalize
__device__ int   d_bar;           // barrier;         reset by finalize

__device__ __forceinline__ float dot4(float4 a, float4 b) {
    return a.x*b.x + a.y*b.y + a.z*b.z + a.w*b.w;
}

__global__ void __launch_bounds__(256, 3)
mega(const float* __restrict__ prot,
     const float* __restrict__ subn,
     const int*   __restrict__ idx,
     const float* __restrict__ Wp,
     const float* __restrict__ bp,
     const float* __restrict__ Ws,
     const float* __restrict__ bs,
     const float* __restrict__ wa,
     const float* __restrict__ sub_out,
     const float* __restrict__ prot_out,
     float* __restrict__ out)
{
    __shared__ float sv[D];           // staged v
    __shared__ float su[D];           // staged u
    __shared__ int   s_tk[2];
    __shared__ float sacc[8][32];
    __shared__ float ssumL[32];
    __shared__ float sg[256 + KERN];
    __shared__ float ss[256 + KERN];
    __shared__ float bval[256];
    __shared__ int   bidx[256];
    __shared__ int   s_last, s_top;
    __shared__ float attn[KERN];
    __shared__ float wrow[D];
    __shared__ float ts[DP];
    __shared__ float tpart[DP];
    __shared__ float dprot[D];
    __shared__ float dsub[D];

    int b    = blockIdx.x;
    int t    = threadIdx.x;
    int warp = t >> 5;
    int lane = t & 31;

    // ---------------- producer prologue ----------------
    if (b < 32) {
        // v/u: one warp per Wp row, single coalesced float4 load
        int row = b * 8 + warp;
        float4 w = ((const float4*)(Wp + (size_t)row * DP))[lane];
        float4 a = ((const float4*)wa)[lane];
        float vv = dot4(w, a);
        float uu = w.x + w.y + w.z + w.w;
        #pragma unroll
        for (int o = 16; o > 0; o >>= 1) {
            vv += __shfl_xor_sync(0xffffffffu, vv, o);
            uu += __shfl_xor_sync(0xffffffffu, uu, o);
        }
        if (lane == 0) { d_v[row] = vv; d_u[row] = uu; }
        __syncthreads();
        if (t == 0) { __threadfence(); atomicAdd(&d_vu_done, 1); }
    } else if (b < 32 + N_RPART) {
        // reaction partial over j-slice [j0, j0+32)
        int r  = b - 32;
        int j0 = r * 32;
        int col  = t & 31;
        int row8 = t >> 5;
        float acc = 0.f;
        #pragma unroll
        for (int p = 0; p < 8; p++)
            acc += subn[(size_t)idx[p * 8 + row8] * D + j0 + col];
        sacc[row8][col] = acc;
        __syncthreads();
        if (t < 32) {
            float s = 0.f;
            #pragma unroll
            for (int r8 = 0; r8 < 8; r8++) s += sacc[r8][t];
            ssumL[t] = s;
        }
        __syncthreads();
        if (t < DP) {
            float p = 0.f;
            #pragma unroll
            for (int j = 0; j < 32; j++)
                p += ssumL[j] * Ws[(j0 + j) * DP + t];
            d_react_part[r * DP + t] = p;
        }
    } else if (b == NBLK - 1) {
        // idx tail (outside the ticket space; b=443 is odd -> not a window block)
        if (t < N_INT)
            out[(size_t)(N_PROT + N_SUB) * D + t] = (float)idx[t];
    }

    // ---------------- stage v/u to shared (all blocks) ----------------
    if (t == 0)
        while (((volatile int*)&d_vu_done)[0] < 32) __nanosleep(32);
    __syncthreads();
    sv[t] = d_v[t];
    su[t] = d_u[t];

    // ---------------- phase A: stolen chunks, depth-2 pipelined ----------------
    if (t == 0) {
        s_tk[0] = atomicAdd(&d_work, 1);
        s_tk[1] = atomicAdd(&d_work, 1);
    }
    __syncthreads();
    {
        const float4* sv4 = (const float4*)sv;
        const float4* su4 = (const float4*)su;
        float4 va = sv4[lane], vc = sv4[lane + 32];
        float4 ua = su4[lane], uc = su4[lane + 32];

        int cur = s_tk[0];
        int nxt = s_tk[1];
        int p   = 0;

        float4 a0, c0, a1, c1;
        if (cur < NTICK) {
            const float4* src = (cur < TK_PROT)
                ? (const float4*)(prot + (size_t)(cur * 16 + warp * 2) * D)
                : (const float4*)(subn + (size_t)((cur - TK_PROT) * 16 + warp * 2) * D);
            a0 = src[lane];
            c0 = src[lane + 32];
            a1 = src[64 + lane];
            c1 = src[64 + lane + 32];
        }

        while (cur < NTICK) {
            if (t == 0) s_tk[p] = atomicAdd(&d_work, 1);   // overlapped prefetch

            float4 n0, n1, n2, n3;
            bool hn = (nxt < NTICK);
            if (hn) {
                const float4* nsrc = (nxt < TK_PROT)
                    ? (const float4*)(prot + (size_t)(nxt * 16 + warp * 2) * D)
                    : (const float4*)(subn + (size_t)((nxt - TK_PROT) * 16 + warp * 2) * D);
                n0 = nsrc[lane];
                n1 = nsrc[lane + 32];
                n2 = nsrc[64 + lane];
                n3 = nsrc[64 + lane + 32];
            }

            if (cur < TK_PROT) {
                int row = cur * 16 + warp * 2;
                float4* dst = (float4*)(out + (size_t)row * D);
                dst[lane]           = a0;
                dst[lane + 32]      = c0;
                dst[64 + lane]      = a1;
                dst[64 + lane + 32] = c1;

                float g0 = dot4(a0, va) + dot4(c0, vc);
                float s0 = dot4(a0, ua) + dot4(c0, uc);
                float g1 = dot4(a1, va) + dot4(c1, vc);
                float s1 = dot4(a1, ua) + dot4(c1, uc);
                #pragma unroll
                for (int o = 16; o > 0; o >>= 1) {
                    g0 += __shfl_down_sync(0xffffffffu, g0, o);
                    s0 += __shfl_down_sync(0xffffffffu, s0, o);
                    g1 += __shfl_down_sync(0xffffffffu, g1, o);
                    s1 += __shfl_down_sync(0xffffffffu, s1, o);
                }
                if (lane == 0) {
                    d_g[row]     = g0;  d_s[row]     = s0;
                    d_g[row + 1] = g1;  d_s[row + 1] = s1;
                }
            } else {
                int row = (cur - TK_PROT) * 16 + warp * 2;
                float4* dst = (float4*)(out + (size_t)(N_PROT + row) * D);
                dst[lane]           = a0;
                dst[lane + 32]      = c0;
                dst[64 + lane]      = a1;
                dst[64 + lane + 32] = c1;
            }

            __syncthreads();          // publish prefetched ticket
            cur = nxt;
            a0 = n0; c0 = n1; a1 = n2; c1 = n3;
            nxt = s_tk[p];
            p ^= 1;
        }
    }

    // ---------------- grid barrier (arrive; non-phase-B exit) ----------------
    __syncthreads();
    if (t == 0) {
        __threadfence();
        atomicAdd(&d_bar, 1);
    }
    bool isWin = ((b & 1) == 0) && ((b >> 1) < NB_WIN);   // 196 even blocks
    if (!isWin) return;
    int wb = b >> 1;                    // window-block id, 0..195
    if (t == 0) {
        while (((volatile int*)&d_bar)[0] < NBLK) __nanosleep(64);
        __threadfence();
    }
    __syncthreads();

    // ---------------- phase B: windows + block argmax ----------------
    {
        int base = wb * 256;
        for (int i = t; i < 256 + KERN - 1; i += 256) {
            int gi = base + i;
            sg[i] = (gi < N_PROT) ? d_g[gi] : -FLT_MAX;
            ss[i] = (gi < N_PROT) ? d_s[gi] : 0.f;
        }
        __syncthreads();

        int   w = base + t;
        float A = -FLT_MAX;
        if (w < NW) {
            float m = sg[t];
            #pragma unroll
            for (int k = 1; k < KERN; k++) m = fmaxf(m, sg[t + k]);
            float wsum = 0.f, asum = 0.f;
            #pragma unroll
            for (int k = 0; k < KERN; k++) {
                float e = expf(sg[t + k] - m);
                wsum += e;
                asum += e * ss[t + k];
            }
            A = asum / wsum;
        }
        bval[t] = A;
        bidx[t] = w;
        __syncthreads();

        for (int off = 128; off > 0; off >>= 1) {
            if (t < off) {
                float ov = bval[t + off];
                int   oi = bidx[t + off];
                if (ov > bval[t] || (ov == bval[t] && oi < bidx[t])) {
                    bval[t] = ov;
                    bidx[t] = oi;
                }
            }
            __syncthreads();
        }
        if (t == 0) {
            d_blkVal[wb] = bval[0];
            d_blkIdx[wb] = bidx[0];
        }
    }

    // ---------------- ticket among window blocks: last finalizes ----------------
    __syncthreads();
    if (t == 0) {
        __threadfence();
        s_last = (atomicAdd(&d_count, 1) == NB_WIN - 1);
    }
    __syncthreads();
    if (!s_last) return;

    // reduce 196 candidates -> top
    if (t < NB_WIN) { bval[t] = d_blkVal[t]; bidx[t] = d_blkIdx[t]; }
    else            { bval[t] = -FLT_MAX;    bidx[t] = 0x7fffffff; }
    __syncthreads();
    for (int off = 128; off > 0; off >>= 1) {
        if (t < off) {
            float ov = bval[t + off];
            int   oi = bidx[t + off];
            if (ov > bval[t] || (ov == bval[t] && oi < bidx[t])) {
                bval[t] = ov;
                bidx[t] = oi;
            }
        }
        __syncthreads();
    }
    if (t == 0) {
        s_top = bidx[0];
        d_count = 0; d_vu_done = 0; d_bar = 0; d_work = 0;  // reset for replay
    }
    __syncthreads();
    int top = s_top;

    // attn (one warp)
    if (t < 32) {
        float gk = (t < KERN) ? d_g[top + t] : -FLT_MAX;
        float m = gk;
        #pragma unroll
        for (int o = 16; o > 0; o >>= 1)
            m = fmaxf(m, __shfl_xor_sync(0xffffffffu, m, o));
        float e = (t < KERN) ? expf(gk - m) : 0.f;
        float sum = e;
        #pragma unroll
        for (int o = 16; o > 0; o >>= 1)
            sum += __shfl_xor_sync(0xffffffffu, sum, o);
        if (t < KERN) attn[t] = e / sum;
    }
    __syncthreads();

    // weighted prot row
    {
        float acc = 0.f;
        #pragma unroll
        for (int k = 0; k < KERN; k++)
            acc += attn[k] * prot[(size_t)(top + k) * D + t];
        wrow[t] = acc;
    }
    __syncthreads();

    // top_score[d] = sum_r react_part[r][d] + 64*bs[d] + bp[d] + wrow @ Wp[:,d]
    {
        int c    = t & (DP - 1);
        int half = t >> 7;
        int j0   = half * (D / 2);
        float acc = 0.f;
        #pragma unroll 32
        for (int j = 0; j < D / 2; j++)
            acc += wrow[j0 + j] * Wp[(j0 + j) * DP + c];
        if (half) tpart[c] = acc;
        __syncthreads();
        if (!half) {
            float rp = 0.f;
            #pragma unroll
            for (int r = 0; r < N_RPART; r++) rp += d_react_part[r * DP + c];
            ts[c] = acc + tpart[c] + rp + (float)N_INT * bs[c] + bp[c];
        }
    }
    __syncthreads();

    // deltas
    {
        float dp_ = 0.f, ds_ = 0.f;
        #pragma unroll 32
        for (int d = 0; d < DP; d++) {
            float s = ts[d];
            dp_ += s * prot_out[d * D + t];
            ds_ += s * sub_out[d * D + t];
        }
        dprot[t] = dp_;
        dsub[t]  = ds_;
    }
    __syncthreads();

    // patch 16 prot rows
    #pragma unroll
    for (int k = 0; k < KERN; k++)
        out[(size_t)(top + k) * D + t] += dprot[t];

    // patch 64 sub rows (set semantics; duplicates identical)
    #pragma unroll 4
    for (int m = 0; m < N_INT; m++) {
        int r = idx[m];
        out[(size_t)(N_PROT + r) * D + t] = subn[(size_t)r * D + t] + dsub[t];
    }
}

// ============================================================
extern "C" void kernel_launch(void* const* d_in, const int* in_sizes, int n_in,
                              void* d_out, int out_size)
{
    const float* prot_node = (const float*)d_in[0];
    const float* sub_node  = (const float*)d_in[1];
    const int*   int_index = (const int*)  d_in[2];
    const float* Wp        = (const float*)d_in[3];
    const float* bp        = (const float*)d_in[4];
    const float* Ws        = (const float*)d_in[5];
    const float* bs        = (const float*)d_in[6];
    const float* wa        = (const float*)d_in[7];
    const float* sub_out   = (const float*)d_in[9];
    const float* prot_out  = (const float*)d_in[10];
    float*       out       = (float*)d_out;

    mega<<<NBLK, 256>>>(prot_node, sub_node, int_index, Wp, bp, Ws, bs, wa,
                        sub_out, prot_out, out);
}